// round 1
// baseline (speedup 1.0000x reference)
#include <cuda_runtime.h>
#include <cuda_bf16.h>

// ---------------------------------------------------------------------------
// MistralAttention baseline (fp32): QKV GEMM -> RoPE -> flash attn -> O GEMM
// B=1, S=2048, H=4096, NH=32, NKV=8, HD=128
// ---------------------------------------------------------------------------

#define S_LEN 2048
#define HID   4096
#define NH    32
#define NKV   8
#define HD    128
#define QDIM  (NH * HD)    // 4096
#define KVDIM (NKV * HD)   // 1024

// Scratch (static device memory — no runtime allocation)
__device__ float g_Q[S_LEN * QDIM];
__device__ float g_K[S_LEN * KVDIM];
__device__ float g_V[S_LEN * KVDIM];
__device__ float g_A[S_LEN * QDIM];

// ---------------------------------------------------------------------------
// Classic 128x128x8 SGEMM, row-major: C[M,N] = A[M,K] @ B[K,N]
// 256 threads, 8x8 accumulator per thread.
// ---------------------------------------------------------------------------
__global__ __launch_bounds__(256) void sgemm128(const float* __restrict__ A,
                                                const float* __restrict__ B,
                                                float* __restrict__ C,
                                                int M, int N, int K) {
    __shared__ float As[8][128];   // transposed A tile
    __shared__ float Bs[8][128];

    const int tid = threadIdx.x;
    const int tx = tid & 15;       // 0..15
    const int ty = tid >> 4;       // 0..15
    const int bx = blockIdx.x;
    const int by = blockIdx.y;

    const int a_row  = tid >> 1;          // 0..127
    const int a_col  = (tid & 1) * 4;     // 0 or 4
    const int b_row  = tid >> 5;          // 0..7
    const int b_col  = (tid & 31) * 4;    // 0..124

    const float* Ag = A + (size_t)(by * 128 + a_row) * K + a_col;
    const float* Bg = B + (size_t)b_row * N + bx * 128 + b_col;

    float acc[8][8];
#pragma unroll
    for (int i = 0; i < 8; i++)
#pragma unroll
        for (int j = 0; j < 8; j++) acc[i][j] = 0.f;

    for (int k0 = 0; k0 < K; k0 += 8) {
        float4 av = *(const float4*)(Ag + k0);
        float4 bv = *(const float4*)(Bg + (size_t)k0 * N);
        As[a_col + 0][a_row] = av.x;
        As[a_col + 1][a_row] = av.y;
        As[a_col + 2][a_row] = av.z;
        As[a_col + 3][a_row] = av.w;
        *(float4*)&Bs[b_row][b_col] = bv;
        __syncthreads();

#pragma unroll
        for (int k = 0; k < 8; k++) {
            float ar[8], br[8];
            *(float4*)&ar[0] = *(const float4*)&As[k][ty * 8];
            *(float4*)&ar[4] = *(const float4*)&As[k][ty * 8 + 4];
            *(float4*)&br[0] = *(const float4*)&Bs[k][tx * 8];
            *(float4*)&br[4] = *(const float4*)&Bs[k][tx * 8 + 4];
#pragma unroll
            for (int i = 0; i < 8; i++)
#pragma unroll
                for (int j = 0; j < 8; j++)
                    acc[i][j] += ar[i] * br[j];
        }
        __syncthreads();
    }

#pragma unroll
    for (int i = 0; i < 8; i++) {
        int row = by * 128 + ty * 8 + i;
        float* Cp = C + (size_t)row * N + bx * 128 + tx * 8;
        float4 o0 = make_float4(acc[i][0], acc[i][1], acc[i][2], acc[i][3]);
        float4 o1 = make_float4(acc[i][4], acc[i][5], acc[i][6], acc[i][7]);
        *(float4*)(Cp + 0) = o0;
        *(float4*)(Cp + 4) = o1;
    }
}

// ---------------------------------------------------------------------------
// RoPE in-place on X[S, nheads*128]. One thread per (s, h, pair i<64).
// ---------------------------------------------------------------------------
__global__ void rope_kernel(float* __restrict__ X, const int* __restrict__ pos_ids,
                            int nheads, int total) {
    int idx = blockIdx.x * blockDim.x + threadIdx.x;
    if (idx >= total) return;
    int i = idx & 63;
    int h = (idx >> 6) % nheads;
    int s = idx / (64 * nheads);
    // inv_freq = 10000^(-2i/128) = exp(-(2i/128)*ln(10000))
    float inv = __expf(-(float)(2 * i) * (9.210340371976184f / 128.0f));
    float ang = (float)pos_ids[s] * inv;
    float sn, cs;
    __sincosf(ang, &sn, &cs);
    size_t base = (size_t)s * nheads * 128 + h * 128 + i;
    float x1 = X[base];
    float x2 = X[base + 64];
    X[base]      = x1 * cs - x2 * sn;
    X[base + 64] = x2 * cs + x1 * sn;
}

// ---------------------------------------------------------------------------
// fp32 flash attention, causal. BM=BN=64, D=128, 256 threads.
// S-tile mapping : rows 4*ty+i (i<4), cols tx+16*j (j<4)
// O-tile mapping : rows 4*ty+i (i<4), cols 8*tx+j (j<8)
// K and V share one smem buffer (K consumed before V load).
// ---------------------------------------------------------------------------
#define KV_STRIDE 132
#define P_STRIDE  68

extern __shared__ float fsm[];

__global__ __launch_bounds__(256) void flash_kernel(const float* __restrict__ Q,
                                                    const float* __restrict__ K,
                                                    const float* __restrict__ V,
                                                    float* __restrict__ O) {
    float* Qs  = fsm;                   // 64 * 132
    float* KVs = Qs + 64 * KV_STRIDE;   // 64 * 132
    float* Ps  = KVs + 64 * KV_STRIDE;  // 64 * 68

    const int h  = blockIdx.x;          // 0..31
    const int qb = blockIdx.y;          // 0..31
    const int kh = h >> 2;              // GQA: 4 q heads per kv head
    const int tid = threadIdx.x;
    const int tx = tid & 15;
    const int ty = tid >> 4;
    const float scale = 0.08838834764831845f;  // 1/sqrt(128)

    // Load Q tile [64,128]
    const float* Qg = Q + (size_t)(qb * 64) * QDIM + h * HD;
    for (int t = tid; t < 64 * 32; t += 256) {
        int r = t >> 5, c4 = t & 31;
        *(float4*)&Qs[r * KV_STRIDE + c4 * 4] = *(const float4*)(Qg + (size_t)r * QDIM + c4 * 4);
    }

    float o[4][8];
    float m[4], l[4];
#pragma unroll
    for (int i = 0; i < 4; i++) {
        m[i] = -1e30f;
        l[i] = 0.f;
#pragma unroll
        for (int j = 0; j < 8; j++) o[i][j] = 0.f;
    }

    const int ntiles = qb + 1;
    for (int t = 0; t < ntiles; t++) {
        __syncthreads();  // previous PV reads of KVs/Ps done; Qs load done (t=0)

        // Load K tile [64,128]
        const float* Kg = K + (size_t)(t * 64) * KVDIM + kh * HD;
        for (int u = tid; u < 64 * 32; u += 256) {
            int r = u >> 5, c4 = u & 31;
            *(float4*)&KVs[r * KV_STRIDE + c4 * 4] = *(const float4*)(Kg + (size_t)r * KVDIM + c4 * 4);
        }
        __syncthreads();

        // S = Q @ K^T
        float s[4][4];
#pragma unroll
        for (int i = 0; i < 4; i++)
#pragma unroll
            for (int j = 0; j < 4; j++) s[i][j] = 0.f;

#pragma unroll 4
        for (int k = 0; k < 128; k++) {
            float a[4], b[4];
#pragma unroll
            for (int i = 0; i < 4; i++) a[i] = Qs[(4 * ty + i) * KV_STRIDE + k];
#pragma unroll
            for (int j = 0; j < 4; j++) b[j] = KVs[(tx + 16 * j) * KV_STRIDE + k];
#pragma unroll
            for (int i = 0; i < 4; i++)
#pragma unroll
                for (int j = 0; j < 4; j++) s[i][j] += a[i] * b[j];
        }

        const bool diag = (t == qb);
#pragma unroll
        for (int i = 0; i < 4; i++) {
            int rg = qb * 64 + 4 * ty + i;
#pragma unroll
            for (int j = 0; j < 4; j++) {
                float sv = s[i][j] * scale;
                if (diag) {
                    int cg = t * 64 + tx + 16 * j;
                    if (cg > rg) sv = -1e30f;
                }
                s[i][j] = sv;
            }
        }

        // Online softmax (row groups = 16 lanes sharing ty)
#pragma unroll
        for (int i = 0; i < 4; i++) {
            float mx = s[i][0];
#pragma unroll
            for (int j = 1; j < 4; j++) mx = fmaxf(mx, s[i][j]);
#pragma unroll
            for (int off = 1; off < 16; off <<= 1)
                mx = fmaxf(mx, __shfl_xor_sync(0xffffffffu, mx, off, 16));
            float mnew = fmaxf(m[i], mx);
            float alpha = __expf(m[i] - mnew);
            float rsum = 0.f;
#pragma unroll
            for (int j = 0; j < 4; j++) {
                float p = __expf(s[i][j] - mnew);
                s[i][j] = p;
                rsum += p;
            }
#pragma unroll
            for (int off = 1; off < 16; off <<= 1)
                rsum += __shfl_xor_sync(0xffffffffu, rsum, off, 16);
            l[i] = l[i] * alpha + rsum;
            m[i] = mnew;
#pragma unroll
            for (int j = 0; j < 8; j++) o[i][j] *= alpha;
#pragma unroll
            for (int j = 0; j < 4; j++)
                Ps[(4 * ty + i) * P_STRIDE + tx + 16 * j] = s[i][j];
        }
        __syncthreads();  // K reads + P writes complete

        // Load V tile into the same buffer
        const float* Vg = V + (size_t)(t * 64) * KVDIM + kh * HD;
        for (int u = tid; u < 64 * 32; u += 256) {
            int r = u >> 5, c4 = u & 31;
            *(float4*)&KVs[r * KV_STRIDE + c4 * 4] = *(const float4*)(Vg + (size_t)r * KVDIM + c4 * 4);
        }
        __syncthreads();

        // O += P @ V
#pragma unroll 2
        for (int k = 0; k < 64; k++) {
            float p[4];
#pragma unroll
            for (int i = 0; i < 4; i++) p[i] = Ps[(4 * ty + i) * P_STRIDE + k];
            float4 v0 = *(const float4*)&KVs[k * KV_STRIDE + 8 * tx];
            float4 v1 = *(const float4*)&KVs[k * KV_STRIDE + 8 * tx + 4];
#pragma unroll
            for (int i = 0; i < 4; i++) {
                o[i][0] += p[i] * v0.x;
                o[i][1] += p[i] * v0.y;
                o[i][2] += p[i] * v0.z;
                o[i][3] += p[i] * v0.w;
                o[i][4] += p[i] * v1.x;
                o[i][5] += p[i] * v1.y;
                o[i][6] += p[i] * v1.z;
                o[i][7] += p[i] * v1.w;
            }
        }
    }

    // Normalize and store
#pragma unroll
    for (int i = 0; i < 4; i++) {
        float inv = 1.f / l[i];
        int rg = qb * 64 + 4 * ty + i;
        float* Op = O + (size_t)rg * QDIM + h * HD + 8 * tx;
        float4 o0 = make_float4(o[i][0] * inv, o[i][1] * inv, o[i][2] * inv, o[i][3] * inv);
        float4 o1 = make_float4(o[i][4] * inv, o[i][5] * inv, o[i][6] * inv, o[i][7] * inv);
        *(float4*)(Op + 0) = o0;
        *(float4*)(Op + 4) = o1;
    }
}

// ---------------------------------------------------------------------------
// kernel_launch
// Inputs: 0=hidden_states (2048*4096 f32), 1=attention_mask (unused, causal),
//         2=position_ids (2048 i32), 3=Wq (4096*4096), 4=Wk (4096*1024),
//         5=Wv (4096*1024), 6=Wo (4096*4096). Output: 2048*4096 f32.
// ---------------------------------------------------------------------------
extern "C" void kernel_launch(void* const* d_in, const int* in_sizes, int n_in,
                              void* d_out, int out_size) {
    (void)in_sizes; (void)n_in; (void)out_size;
    const float* X   = (const float*)d_in[0];
    const int*   pos = (const int*)d_in[2];
    const float* Wq  = (const float*)d_in[3];
    const float* Wk  = (const float*)d_in[4];
    const float* Wv  = (const float*)d_in[5];
    const float* Wo  = (const float*)d_in[6];
    float* out = (float*)d_out;

    float *Qp, *Kp, *Vp, *Ap;
    cudaGetSymbolAddress((void**)&Qp, g_Q);
    cudaGetSymbolAddress((void**)&Kp, g_K);
    cudaGetSymbolAddress((void**)&Vp, g_V);
    cudaGetSymbolAddress((void**)&Ap, g_A);

    // QKV projections
    sgemm128<<<dim3(QDIM / 128, S_LEN / 128), 256>>>(X, Wq, Qp, S_LEN, QDIM, HID);
    sgemm128<<<dim3(KVDIM / 128, S_LEN / 128), 256>>>(X, Wk, Kp, S_LEN, KVDIM, HID);
    sgemm128<<<dim3(KVDIM / 128, S_LEN / 128), 256>>>(X, Wv, Vp, S_LEN, KVDIM, HID);

    // RoPE on Q and K
    {
        int totQ = S_LEN * NH * 64;
        int totK = S_LEN * NKV * 64;
        rope_kernel<<<(totQ + 255) / 256, 256>>>(Qp, pos, NH, totQ);
        rope_kernel<<<(totK + 255) / 256, 256>>>(Kp, pos, NKV, totK);
    }

    // Flash attention
    {
        size_t smem = (size_t)(64 * KV_STRIDE * 2 + 64 * P_STRIDE) * sizeof(float);
        cudaFuncSetAttribute(flash_kernel, cudaFuncAttributeMaxDynamicSharedMemorySize, (int)smem);
        flash_kernel<<<dim3(NH, S_LEN / 64), 256, smem>>>(Qp, Kp, Vp, Ap);
    }

    // Output projection
    sgemm128<<<dim3(HID / 128, S_LEN / 128), 256>>>(Ap, Wo, out, S_LEN, HID, HID);
}

// round 3
// speedup vs baseline: 2.0058x; 2.0058x over previous
#include <cuda_runtime.h>
#include <cuda_bf16.h>
#include <cstdint>

// ---------------------------------------------------------------------------
// MistralAttention: mma.sync bf16 (3x split) projections + fp32 flash attn
// B=1, S=2048, H=4096, NH=32, NKV=8, HD=128
// NOTE: harness PTX target is plain sm_103 -> tcgen05 unavailable; use HMMA.
// ---------------------------------------------------------------------------

#define S_LEN 2048
#define HID   4096
#define NH    32
#define NKV   8
#define HD    128
#define QDIM  (NH * HD)    // 4096
#define KVDIM (NKV * HD)   // 1024
#define GK    4096         // reduction dim for all projection gemms

// fp32 scratch
__device__ float g_Q[S_LEN * QDIM];
__device__ float g_K[S_LEN * KVDIM];
__device__ float g_V[S_LEN * KVDIM];
__device__ float g_A[S_LEN * QDIM];

// bf16 hi/lo split scratch
__device__ __nv_bfloat16 g_Xhi[S_LEN * HID],  g_Xlo[S_LEN * HID];
__device__ __nv_bfloat16 g_Ahi[S_LEN * QDIM], g_Alo[S_LEN * QDIM];
__device__ __nv_bfloat16 g_Wqt_hi[QDIM * GK],  g_Wqt_lo[QDIM * GK];   // [N,K]
__device__ __nv_bfloat16 g_Wkt_hi[KVDIM * GK], g_Wkt_lo[KVDIM * GK];
__device__ __nv_bfloat16 g_Wvt_hi[KVDIM * GK], g_Wvt_lo[KVDIM * GK];
__device__ __nv_bfloat16 g_Wot_hi[HID * GK],   g_Wot_lo[HID * GK];

__device__ __forceinline__ uint32_t smem_u32(const void* p) {
    uint32_t a;
    asm("{ .reg .u64 t; cvta.to.shared.u64 t, %1; cvt.u32.u64 %0, t; }" : "=r"(a) : "l"(p));
    return a;
}

#define CP_ASYNC16(sa, ga) \
    asm volatile("cp.async.cg.shared.global [%0], [%1], 16;" :: "r"(sa), "l"(ga))
#define CP_COMMIT() asm volatile("cp.async.commit_group;" ::: "memory")
#define CP_WAIT(n)  asm volatile("cp.async.wait_group %0;" :: "n"(n) : "memory")

#define LDMX4(r0, r1, r2, r3, a) \
    asm volatile("ldmatrix.sync.aligned.m8n8.x4.shared.b16 {%0,%1,%2,%3}, [%4];" \
                 : "=r"(r0), "=r"(r1), "=r"(r2), "=r"(r3) : "r"(a))

#define MMA16816(c, a, b) \
    asm volatile("mma.sync.aligned.m16n8k16.row.col.f32.bf16.bf16.f32 " \
                 "{%0,%1,%2,%3}, {%4,%5,%6,%7}, {%8,%9}, {%0,%1,%2,%3};" \
                 : "+f"((c)[0]), "+f"((c)[1]), "+f"((c)[2]), "+f"((c)[3]) \
                 : "r"((a)[0]), "r"((a)[1]), "r"((a)[2]), "r"((a)[3]), \
                   "r"((b)[0]), "r"((b)[1]))

// ---------------------------------------------------------------------------
// Split conversions
// ---------------------------------------------------------------------------
__global__ void split_kernel(const float* __restrict__ X,
                             __nv_bfloat16* __restrict__ hi,
                             __nv_bfloat16* __restrict__ lo, int n4) {
    int i = blockIdx.x * blockDim.x + threadIdx.x;
    if (i >= n4) return;
    float4 v = ((const float4*)X)[i];
    __nv_bfloat16 h0 = __float2bfloat16(v.x), h1 = __float2bfloat16(v.y);
    __nv_bfloat16 h2 = __float2bfloat16(v.z), h3 = __float2bfloat16(v.w);
    __nv_bfloat162 hp0 = __nv_bfloat162(h0, h1), hp1 = __nv_bfloat162(h2, h3);
    __nv_bfloat162 lp0 = __nv_bfloat162(__float2bfloat16(v.x - __bfloat162float(h0)),
                                        __float2bfloat16(v.y - __bfloat162float(h1)));
    __nv_bfloat162 lp1 = __nv_bfloat162(__float2bfloat16(v.z - __bfloat162float(h2)),
                                        __float2bfloat16(v.w - __bfloat162float(h3)));
    ((__nv_bfloat162*)hi)[2 * i]     = hp0;
    ((__nv_bfloat162*)hi)[2 * i + 1] = hp1;
    ((__nv_bfloat162*)lo)[2 * i]     = lp0;
    ((__nv_bfloat162*)lo)[2 * i + 1] = lp1;
}

// W[K,N] row-major -> Wt hi/lo [N,K] row-major
__global__ void transpose_split_kernel(const float* __restrict__ W,
                                       __nv_bfloat16* __restrict__ hi,
                                       __nv_bfloat16* __restrict__ lo,
                                       int Krows, int Ncols) {
    __shared__ float t[32][33];
    int n0 = blockIdx.x * 32, k0 = blockIdx.y * 32;
    int tx = threadIdx.x, ty = threadIdx.y;  // (32, 8)
#pragma unroll
    for (int j = 0; j < 4; j++)
        t[ty + 8 * j][tx] = W[(size_t)(k0 + ty + 8 * j) * Ncols + n0 + tx];
    __syncthreads();
#pragma unroll
    for (int j = 0; j < 4; j++) {
        int n = n0 + ty + 8 * j;
        int k = k0 + tx;
        float v = t[tx][ty + 8 * j];
        __nv_bfloat16 h = __float2bfloat16(v);
        hi[(size_t)n * Krows + k] = h;
        lo[(size_t)n * Krows + k] = __float2bfloat16(v - __bfloat162float(h));
    }
}

// ---------------------------------------------------------------------------
// HMMA GEMM: C[M,N] = A[M,K] * Bt[N,K]^T, 3xBF16 split.
// 128x128 tile, BK=32, 256 threads (warps 4M x 2N, warp tile 32x64).
// Smem row stride = 40 bf16 (80B) -> conflict-free ldmatrix.
// ---------------------------------------------------------------------------
#define BK       32
#define ROW_B    80            // bytes per smem row
#define TILE_B   (128 * ROW_B) // 10240
#define STAGE_B  (4 * TILE_B)  // 40960: Ahi, Alo, Bhi, Blo
#define GEMM_SMEM (2 * STAGE_B)

__global__ __launch_bounds__(256, 1) void gemm_mma(const __nv_bfloat16* __restrict__ Ahi,
                                                   const __nv_bfloat16* __restrict__ Alo,
                                                   const __nv_bfloat16* __restrict__ Bhi,
                                                   const __nv_bfloat16* __restrict__ Blo,
                                                   float* __restrict__ C, int N) {
    extern __shared__ char smem[];
    const uint32_t sb = smem_u32(smem);
    const int tid = threadIdx.x;
    const int wid = tid >> 5, lane = tid & 31;
    const int wm = wid & 3, wn = wid >> 2;       // warp coords: 4 x 2
    const int m0 = blockIdx.y * 128, n0 = blockIdx.x * 128;

    const __nv_bfloat16* gsrc[4] = {
        Ahi + (size_t)m0 * GK, Alo + (size_t)m0 * GK,
        Bhi + (size_t)n0 * GK, Blo + (size_t)n0 * GK
    };
    // per-thread load coords: idx = it*256+tid -> tile=it>>1, r, ch
    const int ld_ch = tid & 3;
    // ldmatrix lane geometry
    const int mat = lane >> 3, r8 = lane & 7;
    // A: row-half = mat&1, k-half = mat>>1
    const uint32_t a_off0 = (uint32_t)((wm * 32 + (mat & 1) * 8 + r8) * ROW_B + (mat >> 1) * 16);
    // B: n-half = mat>>1, k-half = mat&1
    const uint32_t b_off0 = (uint32_t)((wn * 64 + (mat >> 1) * 8 + r8) * ROW_B + (mat & 1) * 16);

    float acc[2][8][4];
#pragma unroll
    for (int mi = 0; mi < 2; mi++)
#pragma unroll
        for (int ni = 0; ni < 8; ni++)
#pragma unroll
            for (int j = 0; j < 4; j++) acc[mi][ni][j] = 0.f;

    const int nchunk = GK / BK;

    // stage loader
    auto load_stage = [&](int c, int s) {
        const int k0 = c * BK;
#pragma unroll
        for (int it = 0; it < 8; it++) {
            int tile = it >> 1;
            int r = ((it * 256 + tid) >> 2) & 127;
            const __nv_bfloat16* g = gsrc[tile] + (size_t)r * GK + k0 + ld_ch * 8;
            uint32_t sa = sb + s * STAGE_B + tile * TILE_B + (uint32_t)(r * ROW_B + ld_ch * 16);
            CP_ASYNC16(sa, g);
        }
        CP_COMMIT();
    };

    load_stage(0, 0);

    for (int c = 0; c < nchunk; c++) {
        const int s = c & 1;
        if (c + 1 < nchunk) {
            load_stage(c + 1, s ^ 1);
            CP_WAIT(1);
        } else {
            CP_WAIT(0);
        }
        __syncthreads();

        const uint32_t sAh = sb + s * STAGE_B;
        const uint32_t sAl = sAh + TILE_B;
        const uint32_t sBh = sAl + TILE_B;
        const uint32_t sBl = sBh + TILE_B;

#pragma unroll
        for (int ks = 0; ks < 2; ks++) {
            const uint32_t kofs = ks * 32;  // 16 bf16 = 32B
            uint32_t ah[2][4], al[2][4], bh[8][2], bl[8][2];
#pragma unroll
            for (int mi = 0; mi < 2; mi++) {
                uint32_t ao = a_off0 + (uint32_t)(mi * 16 * ROW_B) + kofs;
                LDMX4(ah[mi][0], ah[mi][1], ah[mi][2], ah[mi][3], sAh + ao);
                LDMX4(al[mi][0], al[mi][1], al[mi][2], al[mi][3], sAl + ao);
            }
#pragma unroll
            for (int nj = 0; nj < 4; nj++) {
                uint32_t bo = b_off0 + (uint32_t)(nj * 16 * ROW_B) + kofs;
                LDMX4(bh[2 * nj][0], bh[2 * nj][1], bh[2 * nj + 1][0], bh[2 * nj + 1][1], sBh + bo);
                LDMX4(bl[2 * nj][0], bl[2 * nj][1], bl[2 * nj + 1][0], bl[2 * nj + 1][1], sBl + bo);
            }
#pragma unroll
            for (int mi = 0; mi < 2; mi++)
#pragma unroll
                for (int ni = 0; ni < 8; ni++) {
                    MMA16816(acc[mi][ni], ah[mi], bh[ni]);
                    MMA16816(acc[mi][ni], ah[mi], bl[ni]);
                    MMA16816(acc[mi][ni], al[mi], bh[ni]);
                }
        }
        __syncthreads();  // all warps done with stage s before it is reloaded
    }

    // epilogue: c frag -> rows (lane/4, lane/4+8), cols 2*(lane%4)
#pragma unroll
    for (int mi = 0; mi < 2; mi++) {
        int row = m0 + wm * 32 + mi * 16 + (lane >> 2);
#pragma unroll
        for (int ni = 0; ni < 8; ni++) {
            int col = n0 + wn * 64 + ni * 8 + (lane & 3) * 2;
            float* p0 = C + (size_t)row * N + col;
            float* p1 = p0 + (size_t)8 * N;
            *(float2*)p0 = make_float2(acc[mi][ni][0], acc[mi][ni][1]);
            *(float2*)p1 = make_float2(acc[mi][ni][2], acc[mi][ni][3]);
        }
    }
}

// ---------------------------------------------------------------------------
// RoPE in-place on X[S, nheads*128]
// ---------------------------------------------------------------------------
__global__ void rope_kernel(float* __restrict__ X, const int* __restrict__ pos_ids,
                            int nheads, int total) {
    int idx = blockIdx.x * blockDim.x + threadIdx.x;
    if (idx >= total) return;
    int i = idx & 63;
    int h = (idx >> 6) % nheads;
    int s = idx / (64 * nheads);
    float inv = __expf(-(float)(2 * i) * (9.210340371976184f / 128.0f));
    float ang = (float)pos_ids[s] * inv;
    float sn, cs;
    __sincosf(ang, &sn, &cs);
    size_t base = (size_t)s * nheads * 128 + h * 128 + i;
    float x1 = X[base];
    float x2 = X[base + 64];
    X[base]      = x1 * cs - x2 * sn;
    X[base + 64] = x2 * cs + x1 * sn;
}

// ---------------------------------------------------------------------------
// fp32 flash attention, causal. BM=BN=64, D=128, 256 threads.
// ---------------------------------------------------------------------------
#define KV_STRIDE 132
#define P_STRIDE  68

__global__ __launch_bounds__(256) void flash_kernel(const float* __restrict__ Q,
                                                    const float* __restrict__ K,
                                                    const float* __restrict__ V,
                                                    float* __restrict__ O) {
    extern __shared__ float fsm[];
    float* Qs  = fsm;
    float* KVs = Qs + 64 * KV_STRIDE;
    float* Ps  = KVs + 64 * KV_STRIDE;

    const int h  = blockIdx.x;
    const int qb = blockIdx.y;
    const int kh = h >> 2;
    const int tid = threadIdx.x;
    const int tx = tid & 15;
    const int ty = tid >> 4;
    const float scale = 0.08838834764831845f;

    const float* Qg = Q + (size_t)(qb * 64) * QDIM + h * HD;
    for (int t = tid; t < 64 * 32; t += 256) {
        int r = t >> 5, c4 = t & 31;
        *(float4*)&Qs[r * KV_STRIDE + c4 * 4] = *(const float4*)(Qg + (size_t)r * QDIM + c4 * 4);
    }

    float o[4][8];
    float m[4], l[4];
#pragma unroll
    for (int i = 0; i < 4; i++) {
        m[i] = -1e30f;
        l[i] = 0.f;
#pragma unroll
        for (int j = 0; j < 8; j++) o[i][j] = 0.f;
    }

    const int ntiles = qb + 1;
    for (int t = 0; t < ntiles; t++) {
        __syncthreads();

        const float* Kg = K + (size_t)(t * 64) * KVDIM + kh * HD;
        for (int u = tid; u < 64 * 32; u += 256) {
            int r = u >> 5, c4 = u & 31;
            *(float4*)&KVs[r * KV_STRIDE + c4 * 4] = *(const float4*)(Kg + (size_t)r * KVDIM + c4 * 4);
        }
        __syncthreads();

        float s[4][4];
#pragma unroll
        for (int i = 0; i < 4; i++)
#pragma unroll
            for (int j = 0; j < 4; j++) s[i][j] = 0.f;

#pragma unroll 4
        for (int k = 0; k < 128; k++) {
            float a[4], b[4];
#pragma unroll
            for (int i = 0; i < 4; i++) a[i] = Qs[(4 * ty + i) * KV_STRIDE + k];
#pragma unroll
            for (int j = 0; j < 4; j++) b[j] = KVs[(tx + 16 * j) * KV_STRIDE + k];
#pragma unroll
            for (int i = 0; i < 4; i++)
#pragma unroll
                for (int j = 0; j < 4; j++) s[i][j] += a[i] * b[j];
        }

        const bool diag = (t == qb);
#pragma unroll
        for (int i = 0; i < 4; i++) {
            int rg = qb * 64 + 4 * ty + i;
#pragma unroll
            for (int j = 0; j < 4; j++) {
                float sv = s[i][j] * scale;
                if (diag) {
                    int cg = t * 64 + tx + 16 * j;
                    if (cg > rg) sv = -1e30f;
                }
                s[i][j] = sv;
            }
        }

#pragma unroll
        for (int i = 0; i < 4; i++) {
            float mx = s[i][0];
#pragma unroll
            for (int j = 1; j < 4; j++) mx = fmaxf(mx, s[i][j]);
#pragma unroll
            for (int off = 1; off < 16; off <<= 1)
                mx = fmaxf(mx, __shfl_xor_sync(0xffffffffu, mx, off, 16));
            float mnew = fmaxf(m[i], mx);
            float alpha = __expf(m[i] - mnew);
            float rsum = 0.f;
#pragma unroll
            for (int j = 0; j < 4; j++) {
                float p = __expf(s[i][j] - mnew);
                s[i][j] = p;
                rsum += p;
            }
#pragma unroll
            for (int off = 1; off < 16; off <<= 1)
                rsum += __shfl_xor_sync(0xffffffffu, rsum, off, 16);
            l[i] = l[i] * alpha + rsum;
            m[i] = mnew;
#pragma unroll
            for (int j = 0; j < 8; j++) o[i][j] *= alpha;
#pragma unroll
            for (int j = 0; j < 4; j++)
                Ps[(4 * ty + i) * P_STRIDE + tx + 16 * j] = s[i][j];
        }
        __syncthreads();

        const float* Vg = V + (size_t)(t * 64) * KVDIM + kh * HD;
        for (int u = tid; u < 64 * 32; u += 256) {
            int r = u >> 5, c4 = u & 31;
            *(float4*)&KVs[r * KV_STRIDE + c4 * 4] = *(const float4*)(Vg + (size_t)r * KVDIM + c4 * 4);
        }
        __syncthreads();

#pragma unroll 2
        for (int k = 0; k < 64; k++) {
            float p[4];
#pragma unroll
            for (int i = 0; i < 4; i++) p[i] = Ps[(4 * ty + i) * P_STRIDE + k];
            float4 v0 = *(const float4*)&KVs[k * KV_STRIDE + 8 * tx];
            float4 v1 = *(const float4*)&KVs[k * KV_STRIDE + 8 * tx + 4];
#pragma unroll
            for (int i = 0; i < 4; i++) {
                o[i][0] += p[i] * v0.x;
                o[i][1] += p[i] * v0.y;
                o[i][2] += p[i] * v0.z;
                o[i][3] += p[i] * v0.w;
                o[i][4] += p[i] * v1.x;
                o[i][5] += p[i] * v1.y;
                o[i][6] += p[i] * v1.z;
                o[i][7] += p[i] * v1.w;
            }
        }
    }

#pragma unroll
    for (int i = 0; i < 4; i++) {
        float inv = 1.f / l[i];
        int rg = qb * 64 + 4 * ty + i;
        float* Op = O + (size_t)rg * QDIM + h * HD + 8 * tx;
        float4 o0 = make_float4(o[i][0] * inv, o[i][1] * inv, o[i][2] * inv, o[i][3] * inv);
        float4 o1 = make_float4(o[i][4] * inv, o[i][5] * inv, o[i][6] * inv, o[i][7] * inv);
        *(float4*)(Op + 0) = o0;
        *(float4*)(Op + 4) = o1;
    }
}

// ---------------------------------------------------------------------------
// kernel_launch
// ---------------------------------------------------------------------------
extern "C" void kernel_launch(void* const* d_in, const int* in_sizes, int n_in,
                              void* d_out, int out_size) {
    (void)in_sizes; (void)n_in; (void)out_size;
    const float* X   = (const float*)d_in[0];
    const int*   pos = (const int*)d_in[2];
    const float* Wq  = (const float*)d_in[3];
    const float* Wk  = (const float*)d_in[4];
    const float* Wv  = (const float*)d_in[5];
    const float* Wo  = (const float*)d_in[6];
    float* out = (float*)d_out;

    float *Qp, *Kp, *Vp, *Ap;
    cudaGetSymbolAddress((void**)&Qp, g_Q);
    cudaGetSymbolAddress((void**)&Kp, g_K);
    cudaGetSymbolAddress((void**)&Vp, g_V);
    cudaGetSymbolAddress((void**)&Ap, g_A);
    __nv_bfloat16 *Xhi, *Xlo, *Ahi, *Alo;
    __nv_bfloat16 *Wqh, *Wql, *Wkh, *Wkl, *Wvh, *Wvl, *Woh, *Wol;
    cudaGetSymbolAddress((void**)&Xhi, g_Xhi);
    cudaGetSymbolAddress((void**)&Xlo, g_Xlo);
    cudaGetSymbolAddress((void**)&Ahi, g_Ahi);
    cudaGetSymbolAddress((void**)&Alo, g_Alo);
    cudaGetSymbolAddress((void**)&Wqh, g_Wqt_hi);
    cudaGetSymbolAddress((void**)&Wql, g_Wqt_lo);
    cudaGetSymbolAddress((void**)&Wkh, g_Wkt_hi);
    cudaGetSymbolAddress((void**)&Wkl, g_Wkt_lo);
    cudaGetSymbolAddress((void**)&Wvh, g_Wvt_hi);
    cudaGetSymbolAddress((void**)&Wvl, g_Wvt_lo);
    cudaGetSymbolAddress((void**)&Woh, g_Wot_hi);
    cudaGetSymbolAddress((void**)&Wol, g_Wot_lo);

    // 1) split hidden states
    split_kernel<<<(S_LEN * HID / 4 + 255) / 256, 256>>>(X, Xhi, Xlo, S_LEN * HID / 4);

    // 2) transpose+split weights
    dim3 tb(32, 8);
    transpose_split_kernel<<<dim3(QDIM / 32, GK / 32), tb>>>(Wq, Wqh, Wql, GK, QDIM);
    transpose_split_kernel<<<dim3(KVDIM / 32, GK / 32), tb>>>(Wk, Wkh, Wkl, GK, KVDIM);
    transpose_split_kernel<<<dim3(KVDIM / 32, GK / 32), tb>>>(Wv, Wvh, Wvl, GK, KVDIM);
    transpose_split_kernel<<<dim3(HID / 32, GK / 32), tb>>>(Wo, Woh, Wol, GK, HID);

    // 3) QKV projections (HMMA)
    cudaFuncSetAttribute(gemm_mma, cudaFuncAttributeMaxDynamicSharedMemorySize, GEMM_SMEM);
    gemm_mma<<<dim3(QDIM / 128, S_LEN / 128), 256, GEMM_SMEM>>>(Xhi, Xlo, Wqh, Wql, Qp, QDIM);
    gemm_mma<<<dim3(KVDIM / 128, S_LEN / 128), 256, GEMM_SMEM>>>(Xhi, Xlo, Wkh, Wkl, Kp, KVDIM);
    gemm_mma<<<dim3(KVDIM / 128, S_LEN / 128), 256, GEMM_SMEM>>>(Xhi, Xlo, Wvh, Wvl, Vp, KVDIM);

    // 4) RoPE
    {
        int totQ = S_LEN * NH * 64;
        int totK = S_LEN * NKV * 64;
        rope_kernel<<<(totQ + 255) / 256, 256>>>(Qp, pos, NH, totQ);
        rope_kernel<<<(totK + 255) / 256, 256>>>(Kp, pos, NKV, totK);
    }

    // 5) flash attention (fp32)
    {
        size_t smem = (size_t)(64 * KV_STRIDE * 2 + 64 * P_STRIDE) * sizeof(float);
        cudaFuncSetAttribute(flash_kernel, cudaFuncAttributeMaxDynamicSharedMemorySize, (int)smem);
        flash_kernel<<<dim3(NH, S_LEN / 64), 256, smem>>>(Qp, Kp, Vp, Ap);
    }

    // 6) O projection (HMMA)
    split_kernel<<<(S_LEN * QDIM / 4 + 255) / 256, 256>>>(Ap, Ahi, Alo, S_LEN * QDIM / 4);
    gemm_mma<<<dim3(HID / 128, S_LEN / 128), 256, GEMM_SMEM>>>(Ahi, Alo, Woh, Wol, out, HID);
}

// round 4
// speedup vs baseline: 2.9258x; 1.4587x over previous
#include <cuda_runtime.h>
#include <cuda_bf16.h>
#include <cuda_fp16.h>
#include <cstdint>

// ---------------------------------------------------------------------------
// MistralAttention: mma.sync bf16 projections + mma.sync flash attention
// B=1, S=2048, H=4096, NH=32, NKV=8, HD=128  (plain sm_103 target: no tcgen05)
// ---------------------------------------------------------------------------

#define S_LEN 2048
#define HID   4096
#define NH    32
#define NKV   8
#define HD    128
#define QDIM  (NH * HD)    // 4096
#define KVDIM (NKV * HD)   // 1024
#define GK    4096

// fp32 scratch
__device__ float g_Q[S_LEN * QDIM];
__device__ float g_K[S_LEN * KVDIM];
__device__ float g_V[S_LEN * KVDIM];

// bf16 hi/lo split scratch
__device__ __nv_bfloat16 g_Xhi[S_LEN * HID],  g_Xlo[S_LEN * HID];
__device__ __nv_bfloat16 g_Ahi[S_LEN * QDIM], g_Alo[S_LEN * QDIM];
__device__ __nv_bfloat16 g_Qhi[S_LEN * QDIM], g_Qlo[S_LEN * QDIM];
__device__ __nv_bfloat16 g_Khi[S_LEN * KVDIM], g_Klo[S_LEN * KVDIM];
__device__ __half        g_Vf16[S_LEN * KVDIM];
__device__ __nv_bfloat16 g_Wqt_hi[QDIM * GK],  g_Wqt_lo[QDIM * GK];
__device__ __nv_bfloat16 g_Wkt_hi[KVDIM * GK], g_Wkt_lo[KVDIM * GK];
__device__ __nv_bfloat16 g_Wvt_hi[KVDIM * GK], g_Wvt_lo[KVDIM * GK];
__device__ __nv_bfloat16 g_Wot_hi[HID * GK],   g_Wot_lo[HID * GK];

__device__ __forceinline__ uint32_t smem_u32(const void* p) {
    uint32_t a;
    asm("{ .reg .u64 t; cvta.to.shared.u64 t, %1; cvt.u32.u64 %0, t; }" : "=r"(a) : "l"(p));
    return a;
}

#define CP_ASYNC16(sa, ga) \
    asm volatile("cp.async.cg.shared.global [%0], [%1], 16;" :: "r"(sa), "l"(ga))
#define CP_COMMIT() asm volatile("cp.async.commit_group;" ::: "memory")
#define CP_WAIT(n)  asm volatile("cp.async.wait_group %0;" :: "n"(n) : "memory")

#define LDMX4(r0, r1, r2, r3, a) \
    asm volatile("ldmatrix.sync.aligned.m8n8.x4.shared.b16 {%0,%1,%2,%3}, [%4];" \
                 : "=r"(r0), "=r"(r1), "=r"(r2), "=r"(r3) : "r"(a))
#define LDMX4T(r0, r1, r2, r3, a) \
    asm volatile("ldmatrix.sync.aligned.m8n8.x4.trans.shared.b16 {%0,%1,%2,%3}, [%4];" \
                 : "=r"(r0), "=r"(r1), "=r"(r2), "=r"(r3) : "r"(a))

#define MMA16816(c, a, b) \
    asm volatile("mma.sync.aligned.m16n8k16.row.col.f32.bf16.bf16.f32 " \
                 "{%0,%1,%2,%3}, {%4,%5,%6,%7}, {%8,%9}, {%0,%1,%2,%3};" \
                 : "+f"((c)[0]), "+f"((c)[1]), "+f"((c)[2]), "+f"((c)[3]) \
                 : "r"((a)[0]), "r"((a)[1]), "r"((a)[2]), "r"((a)[3]), \
                   "r"((b)[0]), "r"((b)[1]))

#define MMAF16(c, a, b0, b1) \
    asm volatile("mma.sync.aligned.m16n8k16.row.col.f32.f16.f16.f32 " \
                 "{%0,%1,%2,%3}, {%4,%5,%6,%7}, {%8,%9}, {%0,%1,%2,%3};" \
                 : "+f"((c)[0]), "+f"((c)[1]), "+f"((c)[2]), "+f"((c)[3]) \
                 : "r"((a)[0]), "r"((a)[1]), "r"((a)[2]), "r"((a)[3]), \
                   "r"(b0), "r"(b1))

// ---------------------------------------------------------------------------
// Conversions
// ---------------------------------------------------------------------------
__global__ void split_kernel(const float* __restrict__ X,
                             __nv_bfloat16* __restrict__ hi,
                             __nv_bfloat16* __restrict__ lo, int n4) {
    int i = blockIdx.x * blockDim.x + threadIdx.x;
    if (i >= n4) return;
    float4 v = ((const float4*)X)[i];
    __nv_bfloat16 h0 = __float2bfloat16(v.x), h1 = __float2bfloat16(v.y);
    __nv_bfloat16 h2 = __float2bfloat16(v.z), h3 = __float2bfloat16(v.w);
    ((__nv_bfloat162*)hi)[2 * i]     = __nv_bfloat162(h0, h1);
    ((__nv_bfloat162*)hi)[2 * i + 1] = __nv_bfloat162(h2, h3);
    ((__nv_bfloat162*)lo)[2 * i]     = __nv_bfloat162(__float2bfloat16(v.x - __bfloat162float(h0)),
                                                      __float2bfloat16(v.y - __bfloat162float(h1)));
    ((__nv_bfloat162*)lo)[2 * i + 1] = __nv_bfloat162(__float2bfloat16(v.z - __bfloat162float(h2)),
                                                      __float2bfloat16(v.w - __bfloat162float(h3)));
}

__global__ void tohalf_kernel(const float* __restrict__ X, __half* __restrict__ Y, int n4) {
    int i = blockIdx.x * blockDim.x + threadIdx.x;
    if (i >= n4) return;
    float4 v = ((const float4*)X)[i];
    ((__half2*)Y)[2 * i]     = __floats2half2_rn(v.x, v.y);
    ((__half2*)Y)[2 * i + 1] = __floats2half2_rn(v.z, v.w);
}

// W[K,N] row-major -> Wt hi/lo [N,K]
__global__ void transpose_split_kernel(const float* __restrict__ W,
                                       __nv_bfloat16* __restrict__ hi,
                                       __nv_bfloat16* __restrict__ lo,
                                       int Krows, int Ncols) {
    __shared__ float t[32][33];
    int n0 = blockIdx.x * 32, k0 = blockIdx.y * 32;
    int tx = threadIdx.x, ty = threadIdx.y;
#pragma unroll
    for (int j = 0; j < 4; j++)
        t[ty + 8 * j][tx] = W[(size_t)(k0 + ty + 8 * j) * Ncols + n0 + tx];
    __syncthreads();
#pragma unroll
    for (int j = 0; j < 4; j++) {
        int n = n0 + ty + 8 * j;
        int k = k0 + tx;
        float v = t[tx][ty + 8 * j];
        __nv_bfloat16 h = __float2bfloat16(v);
        hi[(size_t)n * Krows + k] = h;
        lo[(size_t)n * Krows + k] = __float2bfloat16(v - __bfloat162float(h));
    }
}

// RoPE: read fp32, write bf16 hi/lo
__global__ void rope_split_kernel(const float* __restrict__ X,
                                  __nv_bfloat16* __restrict__ hi,
                                  __nv_bfloat16* __restrict__ lo,
                                  const int* __restrict__ pos_ids,
                                  int nheads, int total) {
    int idx = blockIdx.x * blockDim.x + threadIdx.x;
    if (idx >= total) return;
    int i = idx & 63;
    int h = (idx >> 6) % nheads;
    int s = idx / (64 * nheads);
    float inv = __expf(-(float)(2 * i) * (9.210340371976184f / 128.0f));
    float ang = (float)pos_ids[s] * inv;
    float sn, cs;
    __sincosf(ang, &sn, &cs);
    size_t base = (size_t)s * nheads * 128 + h * 128 + i;
    float x1 = X[base];
    float x2 = X[base + 64];
    float r1 = x1 * cs - x2 * sn;
    float r2 = x2 * cs + x1 * sn;
    __nv_bfloat16 h1 = __float2bfloat16(r1);
    __nv_bfloat16 h2 = __float2bfloat16(r2);
    hi[base]      = h1;
    hi[base + 64] = h2;
    lo[base]      = __float2bfloat16(r1 - __bfloat162float(h1));
    lo[base + 64] = __float2bfloat16(r2 - __bfloat162float(h2));
}

// ---------------------------------------------------------------------------
// HMMA projection GEMM (unchanged from R3)
// ---------------------------------------------------------------------------
#define BK       32
#define ROW_B    80
#define TILE_B   (128 * ROW_B)
#define STAGE_B  (4 * TILE_B)
#define GEMM_SMEM (2 * STAGE_B)

__global__ __launch_bounds__(256, 1) void gemm_mma(const __nv_bfloat16* __restrict__ Ahi,
                                                   const __nv_bfloat16* __restrict__ Alo,
                                                   const __nv_bfloat16* __restrict__ Bhi,
                                                   const __nv_bfloat16* __restrict__ Blo,
                                                   float* __restrict__ C, int N) {
    extern __shared__ char smem[];
    const uint32_t sb = smem_u32(smem);
    const int tid = threadIdx.x;
    const int wid = tid >> 5, lane = tid & 31;
    const int wm = wid & 3, wn = wid >> 2;
    const int m0 = blockIdx.y * 128, n0 = blockIdx.x * 128;

    const __nv_bfloat16* gsrc[4] = {
        Ahi + (size_t)m0 * GK, Alo + (size_t)m0 * GK,
        Bhi + (size_t)n0 * GK, Blo + (size_t)n0 * GK
    };
    const int ld_ch = tid & 3;
    const int mat = lane >> 3, r8 = lane & 7;
    const uint32_t a_off0 = (uint32_t)((wm * 32 + (mat & 1) * 8 + r8) * ROW_B + (mat >> 1) * 16);
    const uint32_t b_off0 = (uint32_t)((wn * 64 + (mat >> 1) * 8 + r8) * ROW_B + (mat & 1) * 16);

    float acc[2][8][4];
#pragma unroll
    for (int mi = 0; mi < 2; mi++)
#pragma unroll
        for (int ni = 0; ni < 8; ni++)
#pragma unroll
            for (int j = 0; j < 4; j++) acc[mi][ni][j] = 0.f;

    const int nchunk = GK / BK;

    auto load_stage = [&](int c, int s) {
        const int k0 = c * BK;
#pragma unroll
        for (int it = 0; it < 8; it++) {
            int tile = it >> 1;
            int r = ((it * 256 + tid) >> 2) & 127;
            const __nv_bfloat16* g = gsrc[tile] + (size_t)r * GK + k0 + ld_ch * 8;
            uint32_t sa = sb + s * STAGE_B + tile * TILE_B + (uint32_t)(r * ROW_B + ld_ch * 16);
            CP_ASYNC16(sa, g);
        }
        CP_COMMIT();
    };

    load_stage(0, 0);

    for (int c = 0; c < nchunk; c++) {
        const int s = c & 1;
        if (c + 1 < nchunk) {
            load_stage(c + 1, s ^ 1);
            CP_WAIT(1);
        } else {
            CP_WAIT(0);
        }
        __syncthreads();

        const uint32_t sAh = sb + s * STAGE_B;
        const uint32_t sAl = sAh + TILE_B;
        const uint32_t sBh = sAl + TILE_B;
        const uint32_t sBl = sBh + TILE_B;

#pragma unroll
        for (int ks = 0; ks < 2; ks++) {
            const uint32_t kofs = ks * 32;
            uint32_t ah[2][4], al[2][4], bh[8][2], bl[8][2];
#pragma unroll
            for (int mi = 0; mi < 2; mi++) {
                uint32_t ao = a_off0 + (uint32_t)(mi * 16 * ROW_B) + kofs;
                LDMX4(ah[mi][0], ah[mi][1], ah[mi][2], ah[mi][3], sAh + ao);
                LDMX4(al[mi][0], al[mi][1], al[mi][2], al[mi][3], sAl + ao);
            }
#pragma unroll
            for (int nj = 0; nj < 4; nj++) {
                uint32_t bo = b_off0 + (uint32_t)(nj * 16 * ROW_B) + kofs;
                LDMX4(bh[2 * nj][0], bh[2 * nj][1], bh[2 * nj + 1][0], bh[2 * nj + 1][1], sBh + bo);
                LDMX4(bl[2 * nj][0], bl[2 * nj][1], bl[2 * nj + 1][0], bl[2 * nj + 1][1], sBl + bo);
            }
#pragma unroll
            for (int mi = 0; mi < 2; mi++)
#pragma unroll
                for (int ni = 0; ni < 8; ni++) {
                    MMA16816(acc[mi][ni], ah[mi], bh[ni]);
                    MMA16816(acc[mi][ni], ah[mi], bl[ni]);
                    MMA16816(acc[mi][ni], al[mi], bh[ni]);
                }
        }
        __syncthreads();
    }

#pragma unroll
    for (int mi = 0; mi < 2; mi++) {
        int row = m0 + wm * 32 + mi * 16 + (lane >> 2);
#pragma unroll
        for (int ni = 0; ni < 8; ni++) {
            int col = n0 + wn * 64 + ni * 8 + (lane & 3) * 2;
            float* p0 = C + (size_t)row * N + col;
            float* p1 = p0 + (size_t)8 * N;
            *(float2*)p0 = make_float2(acc[mi][ni][0], acc[mi][ni][1]);
            *(float2*)p1 = make_float2(acc[mi][ni][2], acc[mi][ni][3]);
        }
    }
}

// ---------------------------------------------------------------------------
// HMMA flash attention. BM=128, BN=64, D=128, 8 warps.
// S = QK^T via 3xBF16 split; P.V in fp16. Causal. Writes Ahi/Alo bf16.
// ---------------------------------------------------------------------------
#define QSTR 272   // 128 bf16 (or half) + 16B pad
#define PSTR 144   // 64 fp16 + 16B pad
#define FS_QH 0
#define FS_QL 34816
#define FS_KH 69632
#define FS_KL 87040
#define FS_V  104448
#define FS_P  121856
#define FLASH_SMEM 140288

__global__ __launch_bounds__(256, 1) void flash_mma(
    const __nv_bfloat16* __restrict__ Qhg, const __nv_bfloat16* __restrict__ Qlg,
    const __nv_bfloat16* __restrict__ Khg, const __nv_bfloat16* __restrict__ Klg,
    const __half* __restrict__ Vg,
    __nv_bfloat16* __restrict__ Ahi, __nv_bfloat16* __restrict__ Alo) {
    extern __shared__ char smem[];
    const uint32_t sb = smem_u32(smem);
    const int h  = blockIdx.x;
    const int qb = (int)gridDim.y - 1 - (int)blockIdx.y;  // heavy CTAs first
    const int khd = h >> 2;
    const int tid = threadIdx.x, wid = tid >> 5, lane = tid & 31;
    const int mat = lane >> 3, r8 = lane & 7;

    // ---- Q tile loads (128 rows x 256B, hi+lo), no commit (joins first K group)
    {
#pragma unroll
        for (int i = 0; i < 16; i++) {
            int idx = i * 256 + tid;
            int buf = idx >> 11, r = (idx >> 4) & 127, c = idx & 15;
            const __nv_bfloat16* g = (buf ? Qlg : Qhg) +
                (size_t)(qb * 128 + r) * QDIM + h * 128 + c * 8;
            CP_ASYNC16(sb + FS_QH + buf * (128 * QSTR) + r * QSTR + c * 16, g);
        }
    }

    // ldmatrix base addresses
    const uint32_t aQh = sb + FS_QH + (uint32_t)((wid * 16 + (mat & 1) * 8 + r8) * QSTR + (mat >> 1) * 16);
    const uint32_t aQl = aQh + (FS_QL - FS_QH);
    const uint32_t bKh = sb + FS_KH + (uint32_t)(((mat >> 1) * 8 + r8) * QSTR + (mat & 1) * 16);
    const uint32_t bKl = bKh + (FS_KL - FS_KH);
    const uint32_t aP  = sb + FS_P + (uint32_t)((wid * 16 + (mat & 1) * 8 + r8) * PSTR + (mat >> 1) * 16);
    const uint32_t bV  = sb + FS_V + (uint32_t)(((mat & 1) * 8 + r8) * QSTR + (mat >> 1) * 16);

    float o[16][4];
#pragma unroll
    for (int nb = 0; nb < 16; nb++)
#pragma unroll
        for (int j = 0; j < 4; j++) o[nb][j] = 0.f;
    float m0 = -1e30f, m1 = -1e30f, l0 = 0.f, l1 = 0.f;

    const float scale2 = 0.12753237f;  // 1/sqrt(128) * log2(e)
    const int row0g = qb * 128 + wid * 16 + (lane >> 2);
    const int ntiles = 2 * qb + 2;

    for (int t = 0; t < ntiles; t++) {
        __syncthreads();  // previous PV done; K/V/P buffers free

        // K tile (hi+lo): group A
#pragma unroll
        for (int i = 0; i < 8; i++) {
            int idx = i * 256 + tid;
            int buf = idx >> 10, r = (idx >> 4) & 63, c = idx & 15;
            const __nv_bfloat16* g = (buf ? Klg : Khg) +
                (size_t)(t * 64 + r) * KVDIM + khd * 128 + c * 8;
            CP_ASYNC16(sb + FS_KH + buf * (64 * QSTR) + r * QSTR + c * 16, g);
        }
        CP_COMMIT();
        // V tile (fp16): group B
#pragma unroll
        for (int i = 0; i < 4; i++) {
            int idx = i * 256 + tid;
            int r = (idx >> 4) & 63, c = idx & 15;
            const __half* g = Vg + (size_t)(t * 64 + r) * KVDIM + khd * 128 + c * 8;
            CP_ASYNC16(sb + FS_V + r * QSTR + c * 16, g);
        }
        CP_COMMIT();
        CP_WAIT(1);        // Q(+first K) / K arrived
        __syncthreads();

        // ---- S = Q K^T (3-term split)
        float sacc[8][4];
#pragma unroll
        for (int nb = 0; nb < 8; nb++)
#pragma unroll
            for (int j = 0; j < 4; j++) sacc[nb][j] = 0.f;

#pragma unroll
        for (int ks = 0; ks < 8; ks++) {
            uint32_t qh[4], ql[4], kh[8][2], kl[8][2];
            LDMX4(qh[0], qh[1], qh[2], qh[3], aQh + ks * 32);
            LDMX4(ql[0], ql[1], ql[2], ql[3], aQl + ks * 32);
#pragma unroll
            for (int nj = 0; nj < 4; nj++) {
                LDMX4(kh[2 * nj][0], kh[2 * nj][1], kh[2 * nj + 1][0], kh[2 * nj + 1][1],
                      bKh + nj * (16 * QSTR) + ks * 32);
                LDMX4(kl[2 * nj][0], kl[2 * nj][1], kl[2 * nj + 1][0], kl[2 * nj + 1][1],
                      bKl + nj * (16 * QSTR) + ks * 32);
            }
#pragma unroll
            for (int nb = 0; nb < 8; nb++) {
                MMA16816(sacc[nb], qh, kh[nb]);
                MMA16816(sacc[nb], qh, kl[nb]);
                MMA16816(sacc[nb], ql, kh[nb]);
            }
        }

        // ---- scale + causal mask (log2 domain)
        const bool maskt = (t >= 2 * qb);
        float mx0 = -1e30f, mx1 = -1e30f;
#pragma unroll
        for (int nb = 0; nb < 8; nb++) {
            float s0 = sacc[nb][0] * scale2, s1 = sacc[nb][1] * scale2;
            float s2 = sacc[nb][2] * scale2, s3 = sacc[nb][3] * scale2;
            if (maskt) {
                int cg = t * 64 + nb * 8 + (lane & 3) * 2;
                if (cg     > row0g)     s0 = -1e30f;
                if (cg + 1 > row0g)     s1 = -1e30f;
                if (cg     > row0g + 8) s2 = -1e30f;
                if (cg + 1 > row0g + 8) s3 = -1e30f;
            }
            sacc[nb][0] = s0; sacc[nb][1] = s1; sacc[nb][2] = s2; sacc[nb][3] = s3;
            mx0 = fmaxf(mx0, fmaxf(s0, s1));
            mx1 = fmaxf(mx1, fmaxf(s2, s3));
        }
        mx0 = fmaxf(mx0, __shfl_xor_sync(0xffffffffu, mx0, 1));
        mx0 = fmaxf(mx0, __shfl_xor_sync(0xffffffffu, mx0, 2));
        mx1 = fmaxf(mx1, __shfl_xor_sync(0xffffffffu, mx1, 1));
        mx1 = fmaxf(mx1, __shfl_xor_sync(0xffffffffu, mx1, 2));

        float mn0 = fmaxf(m0, mx0), mn1 = fmaxf(m1, mx1);
        float a0 = exp2f(m0 - mn0), a1 = exp2f(m1 - mn1);
        float sum0 = 0.f, sum1 = 0.f;

        char* pP0 = smem + FS_P + (wid * 16 + (lane >> 2)) * PSTR + (lane & 3) * 4;
        char* pP1 = pP0 + 8 * PSTR;
#pragma unroll
        for (int nb = 0; nb < 8; nb++) {
            float p0 = exp2f(sacc[nb][0] - mn0);
            float p1 = exp2f(sacc[nb][1] - mn0);
            float p2 = exp2f(sacc[nb][2] - mn1);
            float p3 = exp2f(sacc[nb][3] - mn1);
            sum0 += p0 + p1;
            sum1 += p2 + p3;
            *(__half2*)(pP0 + nb * 16) = __floats2half2_rn(p0, p1);
            *(__half2*)(pP1 + nb * 16) = __floats2half2_rn(p2, p3);
        }
        sum0 += __shfl_xor_sync(0xffffffffu, sum0, 1);
        sum0 += __shfl_xor_sync(0xffffffffu, sum0, 2);
        sum1 += __shfl_xor_sync(0xffffffffu, sum1, 1);
        sum1 += __shfl_xor_sync(0xffffffffu, sum1, 2);
        l0 = l0 * a0 + sum0; l1 = l1 * a1 + sum1;
        m0 = mn0; m1 = mn1;
#pragma unroll
        for (int nb = 0; nb < 16; nb++) {
            o[nb][0] *= a0; o[nb][1] *= a0;
            o[nb][2] *= a1; o[nb][3] *= a1;
        }
        __syncwarp();

        CP_WAIT(0);        // V arrived
        __syncthreads();   // all warps: V visible, P writes visible

        // ---- O += P V (fp16)
#pragma unroll
        for (int kv = 0; kv < 4; kv++) {
            uint32_t pf[4];
            LDMX4(pf[0], pf[1], pf[2], pf[3], aP + kv * 32);
#pragma unroll
            for (int nj = 0; nj < 8; nj++) {
                uint32_t v0, v1, v2, v3;
                LDMX4T(v0, v1, v2, v3, bV + kv * (16 * QSTR) + nj * 32);
                MMAF16(o[2 * nj],     pf, v0, v1);
                MMAF16(o[2 * nj + 1], pf, v2, v3);
            }
        }
    }

    // ---- epilogue: normalize, bf16 hi/lo split, store
    float i0 = 1.f / l0, i1 = 1.f / l1;
    size_t base0 = (size_t)row0g * QDIM + h * 128 + (lane & 3) * 2;
    size_t base1 = base0 + (size_t)8 * QDIM;
#pragma unroll
    for (int nb = 0; nb < 16; nb++) {
        float v0 = o[nb][0] * i0, v1 = o[nb][1] * i0;
        float v2 = o[nb][2] * i1, v3 = o[nb][3] * i1;
        __nv_bfloat16 h0 = __float2bfloat16(v0), h1 = __float2bfloat16(v1);
        __nv_bfloat16 h2 = __float2bfloat16(v2), h3 = __float2bfloat16(v3);
        *(__nv_bfloat162*)(Ahi + base0 + nb * 8) = __nv_bfloat162(h0, h1);
        *(__nv_bfloat162*)(Ahi + base1 + nb * 8) = __nv_bfloat162(h2, h3);
        *(__nv_bfloat162*)(Alo + base0 + nb * 8) =
            __nv_bfloat162(__float2bfloat16(v0 - __bfloat162float(h0)),
                           __float2bfloat16(v1 - __bfloat162float(h1)));
        *(__nv_bfloat162*)(Alo + base1 + nb * 8) =
            __nv_bfloat162(__float2bfloat16(v2 - __bfloat162float(h2)),
                           __float2bfloat16(v3 - __bfloat162float(h3)));
    }
}

// ---------------------------------------------------------------------------
// kernel_launch
// ---------------------------------------------------------------------------
extern "C" void kernel_launch(void* const* d_in, const int* in_sizes, int n_in,
                              void* d_out, int out_size) {
    (void)in_sizes; (void)n_in; (void)out_size;
    const float* X   = (const float*)d_in[0];
    const int*   pos = (const int*)d_in[2];
    const float* Wq  = (const float*)d_in[3];
    const float* Wk  = (const float*)d_in[4];
    const float* Wv  = (const float*)d_in[5];
    const float* Wo  = (const float*)d_in[6];
    float* out = (float*)d_out;

    float *Qp, *Kp, *Vp;
    cudaGetSymbolAddress((void**)&Qp, g_Q);
    cudaGetSymbolAddress((void**)&Kp, g_K);
    cudaGetSymbolAddress((void**)&Vp, g_V);
    __nv_bfloat16 *Xhi, *Xlo, *Ahi, *Alo, *Qhi, *Qlo, *Khi, *Klo;
    __half* Vf;
    __nv_bfloat16 *Wqh, *Wql, *Wkh, *Wkl, *Wvh, *Wvl, *Woh, *Wol;
    cudaGetSymbolAddress((void**)&Xhi, g_Xhi);
    cudaGetSymbolAddress((void**)&Xlo, g_Xlo);
    cudaGetSymbolAddress((void**)&Ahi, g_Ahi);
    cudaGetSymbolAddress((void**)&Alo, g_Alo);
    cudaGetSymbolAddress((void**)&Qhi, g_Qhi);
    cudaGetSymbolAddress((void**)&Qlo, g_Qlo);
    cudaGetSymbolAddress((void**)&Khi, g_Khi);
    cudaGetSymbolAddress((void**)&Klo, g_Klo);
    cudaGetSymbolAddress((void**)&Vf,  g_Vf16);
    cudaGetSymbolAddress((void**)&Wqh, g_Wqt_hi);
    cudaGetSymbolAddress((void**)&Wql, g_Wqt_lo);
    cudaGetSymbolAddress((void**)&Wkh, g_Wkt_hi);
    cudaGetSymbolAddress((void**)&Wkl, g_Wkt_lo);
    cudaGetSymbolAddress((void**)&Wvh, g_Wvt_hi);
    cudaGetSymbolAddress((void**)&Wvl, g_Wvt_lo);
    cudaGetSymbolAddress((void**)&Woh, g_Wot_hi);
    cudaGetSymbolAddress((void**)&Wol, g_Wot_lo);

    // 1) split hidden states
    split_kernel<<<(S_LEN * HID / 4 + 255) / 256, 256>>>(X, Xhi, Xlo, S_LEN * HID / 4);

    // 2) transpose+split weights
    dim3 tb(32, 8);
    transpose_split_kernel<<<dim3(QDIM / 32, GK / 32), tb>>>(Wq, Wqh, Wql, GK, QDIM);
    transpose_split_kernel<<<dim3(KVDIM / 32, GK / 32), tb>>>(Wk, Wkh, Wkl, GK, KVDIM);
    transpose_split_kernel<<<dim3(KVDIM / 32, GK / 32), tb>>>(Wv, Wvh, Wvl, GK, KVDIM);
    transpose_split_kernel<<<dim3(HID / 32, GK / 32), tb>>>(Wo, Woh, Wol, GK, HID);

    // 3) QKV projections (HMMA)
    cudaFuncSetAttribute(gemm_mma, cudaFuncAttributeMaxDynamicSharedMemorySize, GEMM_SMEM);
    gemm_mma<<<dim3(QDIM / 128, S_LEN / 128), 256, GEMM_SMEM>>>(Xhi, Xlo, Wqh, Wql, Qp, QDIM);
    gemm_mma<<<dim3(KVDIM / 128, S_LEN / 128), 256, GEMM_SMEM>>>(Xhi, Xlo, Wkh, Wkl, Kp, KVDIM);
    gemm_mma<<<dim3(KVDIM / 128, S_LEN / 128), 256, GEMM_SMEM>>>(Xhi, Xlo, Wvh, Wvl, Vp, KVDIM);

    // 4) RoPE -> bf16 hi/lo; V -> fp16
    {
        int totQ = S_LEN * NH * 64;
        int totK = S_LEN * NKV * 64;
        rope_split_kernel<<<(totQ + 255) / 256, 256>>>(Qp, Qhi, Qlo, pos, NH, totQ);
        rope_split_kernel<<<(totK + 255) / 256, 256>>>(Kp, Khi, Klo, pos, NKV, totK);
        tohalf_kernel<<<(S_LEN * KVDIM / 4 + 255) / 256, 256>>>(Vp, Vf, S_LEN * KVDIM / 4);
    }

    // 5) flash attention (HMMA) -> Ahi/Alo
    cudaFuncSetAttribute(flash_mma, cudaFuncAttributeMaxDynamicSharedMemorySize, FLASH_SMEM);
    flash_mma<<<dim3(NH, S_LEN / 128), 256, FLASH_SMEM>>>(Qhi, Qlo, Khi, Klo, Vf, Ahi, Alo);

    // 6) O projection (HMMA)
    gemm_mma<<<dim3(HID / 128, S_LEN / 128), 256, GEMM_SMEM>>>(Ahi, Alo, Woh, Wol, out, HID);
}